// round 6
// baseline (speedup 1.0000x reference)
#include <cuda_runtime.h>
#include <math.h>

#define N_NODES 16000
#define N_EDGES 256000
#define EPB 256

#define R_CUT 2.5f
#define SQ3   1.7320508075688772f
#define PI_F  3.14159265358979323846f

// ---- scratch (device globals; no allocations allowed) ----
__device__ float g_attn[N_EDGES];
__device__ float g_hv[16 * N_EDGES];      // V-net hidden, [t][e]
__device__ float g_Z[N_NODES];
__device__ float g_qsw[N_NODES * 8];
__device__ float g_qvw[N_NODES * 12];

// scales
#define INV_SQRT32 0.17677669529663687f
#define W2_SCALE   0.051031036307982884f  // (1/sqrt16)*(1/sqrt24)
#define INV_SQRT16 0.25f
#define INV_SQRT8  0.3535533905932738f
#define INV_FAN    0.11180339887498948f   // 1/sqrt(80)
#define RAD_COEF   5.059644256269407f     // sqrt(2/2.5)*sqrt(32)

// ---- packed fp32x2 helpers ----
typedef unsigned long long u64t;

__device__ __forceinline__ u64t pkdup(float a) {
    u64t r; asm("mov.b64 %0, {%1, %1};" : "=l"(r) : "f"(a)); return r;
}
__device__ __forceinline__ float2 up2(u64t v) {
    float2 r; asm("mov.b64 {%0, %1}, %2;" : "=f"(r.x), "=f"(r.y) : "l"(v)); return r;
}
__device__ __forceinline__ void fma2(u64t& d, u64t a, u64t b) {
    asm("fma.rn.f32x2 %0, %1, %2, %3;" : "=l"(d) : "l"(a), "l"(b), "l"(d));
}

// =====================================================================
// Kernel 1: per-node q (pre-contracted with Ws)
// =====================================================================
__global__ void node_prep_kernel(const float* __restrict__ x,
                                 const float* __restrict__ Wq_s,
                                 const float* __restrict__ Wq_v,
                                 const float* __restrict__ Ws_ss,
                                 const float* __restrict__ Ws_vv)
{
    int n = blockIdx.x * blockDim.x + threadIdx.x;
    if (n >= N_NODES) return;
    const float* xr = x + n * 40;

    float xs[16], xv[24];
    #pragma unroll
    for (int i = 0; i < 16; i++) xs[i] = xr[i];
    #pragma unroll
    for (int i = 0; i < 24; i++) xv[i] = xr[16 + i];

    float qs[8];
    #pragma unroll
    for (int o = 0; o < 8; o++) {
        float a = 0.f;
        #pragma unroll
        for (int i = 0; i < 16; i++) a = fmaf(xs[i], __ldg(&Wq_s[i * 8 + o]), a);
        qs[o] = a * INV_SQRT16;
    }
    float qv[12];
    #pragma unroll
    for (int o = 0; o < 4; o++)
        #pragma unroll
        for (int c = 0; c < 3; c++) {
            float a = 0.f;
            #pragma unroll
            for (int i = 0; i < 8; i++) a = fmaf(xv[i * 3 + c], __ldg(&Wq_v[i * 4 + o]), a);
            qv[o * 3 + c] = a * INV_SQRT8;
        }

    #pragma unroll
    for (int p = 0; p < 8; p++) {
        float a = 0.f;
        #pragma unroll
        for (int o = 0; o < 8; o++) a = fmaf(qs[o], __ldg(&Ws_ss[o * 8 + p]), a);
        g_qsw[n * 8 + p] = a * INV_FAN;
    }
    const float invfs = INV_FAN / SQ3;
    #pragma unroll
    for (int p = 0; p < 4; p++)
        #pragma unroll
        for (int c = 0; c < 3; c++) {
            float a = 0.f;
            #pragma unroll
            for (int o = 0; o < 4; o++) a = fmaf(qv[o * 3 + c], __ldg(&Ws_vv[o * 4 + p]), a);
            g_qvw[n * 12 + p * 3 + c] = a * invfs;
        }
}

// =====================================================================
// Kernel 2 (K pass)
// smem: [0,512) Wk1, [512,1024) Wv1,
//       [1024,4096)  KA: [i<16][t<16][12] = ss o0..7 | sv o0..3
//       [4096,5632)  KB: [i<8][t<16][12]  = vv o0..7 | vs o0..3
// =====================================================================
#define KSM_FLOATS 5632

__global__ void __launch_bounds__(EPB)
edge_k_kernel(const float* __restrict__ pos, const float* __restrict__ x,
              const float* __restrict__ Wk1, const float* __restrict__ Wk2,
              const float* __restrict__ Wv1,
              const int* __restrict__ esrc, const int* __restrict__ edst)
{
    extern __shared__ float smem[];
    float* sW1 = smem;
    float* sKA = smem + 1024;
    float* sKB = smem + 4096;
    const int tid = threadIdx.x;

    for (int idx = tid; idx < 512; idx += EPB) sW1[idx] = Wk1[idx] * INV_SQRT32;
    for (int idx = tid; idx < 512; idx += EPB) sW1[512 + idx] = Wv1[idx] * INV_SQRT32;
    for (int idx = tid; idx < 3072; idx += EPB) {
        int i = idx / 192, r = idx - i * 192, t = r / 12, s = r - t * 12;
        int col = (s < 8) ? (i * 8 + s) : (192 + i * 4 + (s - 8));
        sKA[idx] = Wk2[t * 288 + col] * W2_SCALE;
    }
    for (int idx = tid; idx < 1536; idx += EPB) {
        int i = idx / 192, r = idx - i * 192, t = r / 12, s = r - t * 12;
        int col = (s < 8) ? (128 + i * 8 + s) : (256 + i * 4 + (s - 8));
        sKB[idx] = Wk2[t * 288 + col] * W2_SCALE;
    }
    __syncthreads();

    const ulonglong2* sWk1q = (const ulonglong2*)sW1;          // [n*4+q]
    const ulonglong2* sWv1q = (const ulonglong2*)(sW1 + 512);
    const ulonglong2* KA = (const ulonglong2*)sKA;             // [i*48 + t*3 + k]
    const ulonglong2* KB = (const ulonglong2*)sKB;

    const int e = blockIdx.x * EPB + tid;
    const int ns = esrc[e];
    const int nd = edst[e];

    float vx = pos[nd * 3 + 0] - pos[ns * 3 + 0];
    float vy = pos[nd * 3 + 1] - pos[ns * 3 + 1];
    float vz = pos[nd * 3 + 2] - pos[ns * 3 + 2];
    float d = sqrtf(vx * vx + vy * vy + vz * vz);

    if (d >= R_CUT) {           // rad==0 -> k=v=0 -> sim=0 -> attn=1
        g_attn[e] = 1.0f;
        atomicAdd(&g_Z[nd], 1.0f);
        return;
    }

    const float dsafe = fmaxf(d, 1e-6f);
    const float invd  = 1.0f / dsafe;
    const float vh0 = vx * invd, vh1 = vy * invd, vh2 = vz * invd;
    const float y10 = SQ3 * vh0, y11 = SQ3 * vh1, y12 = SQ3 * vh2;
    const float theta = (PI_F / R_CUT) * dsafe;
    const float coef  = RAD_COEF * invd;

    // ---- radial basis via Chebyshev recurrence; both hidden layers ----
    u64t akp[8], avp[8];
    #pragma unroll
    for (int t2 = 0; t2 < 8; t2++) { akp[t2] = 0ull; avp[t2] = 0ull; }
    float sth, cth;
    sincosf(theta, &sth, &cth);
    const float twoc = 2.0f * cth;
    float s_nm1 = 0.f, s_n = sth;
    #pragma unroll 1
    for (int n = 0; n < 32; n++) {
        float r = coef * s_n;
        u64t r2 = pkdup(r);
        const ulonglong2* wk = sWk1q + n * 4;
        const ulonglong2* wv = sWv1q + n * 4;
        #pragma unroll
        for (int q = 0; q < 4; q++) {
            ulonglong2 a = wk[q];
            fma2(akp[2 * q], r2, a.x);
            fma2(akp[2 * q + 1], r2, a.y);
            ulonglong2 b = wv[q];
            fma2(avp[2 * q], r2, b.x);
            fma2(avp[2 * q + 1], r2, b.y);
        }
        float s_nx = fmaf(twoc, s_n, -s_nm1);
        s_nm1 = s_n; s_n = s_nx;
    }
    // silu: hk packed; hv -> global
    u64t hk2[16];
    #pragma unroll
    for (int t2 = 0; t2 < 8; t2++) {
        float2 a = up2(akp[t2]);
        hk2[2 * t2]     = pkdup(a.x / (1.f + __expf(-a.x)));
        hk2[2 * t2 + 1] = pkdup(a.y / (1.f + __expf(-a.y)));
        float2 b = up2(avp[t2]);
        g_hv[(2 * t2) * N_EDGES + e]     = b.x / (1.f + __expf(-b.x));
        g_hv[(2 * t2 + 1) * N_EDGES + e] = b.y / (1.f + __expf(-b.y));
    }

    const float* xrow = x + ns * 40;
    u64t ksp[4];  u64t kvp[3][2];
    #pragma unroll
    for (int p = 0; p < 4; p++) ksp[p] = 0ull;
    #pragma unroll
    for (int c = 0; c < 3; c++) { kvp[c][0] = 0ull; kvp[c][1] = 0ull; }

    // group A: i<16 (ss + sv), 6 independent chains
    #pragma unroll 1
    for (int i = 0; i < 16; i++) {
        float xi = __ldg(&xrow[i]);
        const ulonglong2* Wp = KA + i * 48;
        u64t w0 = 0, w1 = 0, w2 = 0, w3 = 0, w4 = 0, w5 = 0;
        #pragma unroll
        for (int t = 0; t < 16; t++) {
            ulonglong2 q0 = Wp[t * 3], q1 = Wp[t * 3 + 1], q2 = Wp[t * 3 + 2];
            u64t h = hk2[t];
            fma2(w0, h, q0.x); fma2(w1, h, q0.y);
            fma2(w2, h, q1.x); fma2(w3, h, q1.y);
            fma2(w4, h, q2.x); fma2(w5, h, q2.y);
        }
        u64t xi2 = pkdup(xi);
        fma2(ksp[0], xi2, w0); fma2(ksp[1], xi2, w1);
        fma2(ksp[2], xi2, w2); fma2(ksp[3], xi2, w3);
        u64t m0 = pkdup(xi * y10), m1 = pkdup(xi * y11), m2 = pkdup(xi * y12);
        fma2(kvp[0][0], m0, w4); fma2(kvp[0][1], m0, w5);
        fma2(kvp[1][0], m1, w4); fma2(kvp[1][1], m1, w5);
        fma2(kvp[2][0], m2, w4); fma2(kvp[2][1], m2, w5);
    }
    // group B: i<8 (vv + vs)
    #pragma unroll 1
    for (int i = 0; i < 8; i++) {
        float x0 = __ldg(&xrow[16 + i * 3 + 0]);
        float x1 = __ldg(&xrow[16 + i * 3 + 1]);
        float x2 = __ldg(&xrow[16 + i * 3 + 2]);
        float ui = x0 * vh0 + x1 * vh1 + x2 * vh2;
        const ulonglong2* Wp = KB + i * 48;
        u64t w0 = 0, w1 = 0, w2 = 0, w3 = 0, w4 = 0, w5 = 0;
        #pragma unroll
        for (int t = 0; t < 16; t++) {
            ulonglong2 q0 = Wp[t * 3], q1 = Wp[t * 3 + 1], q2 = Wp[t * 3 + 2];
            u64t h = hk2[t];
            fma2(w0, h, q0.x); fma2(w1, h, q0.y);
            fma2(w2, h, q1.x); fma2(w3, h, q1.y);
            fma2(w4, h, q2.x); fma2(w5, h, q2.y);
        }
        u64t u2 = pkdup(ui);
        fma2(ksp[0], u2, w0); fma2(ksp[1], u2, w1);
        fma2(ksp[2], u2, w2); fma2(ksp[3], u2, w3);
        u64t p0 = pkdup(x0), p1 = pkdup(x1), p2 = pkdup(x2);
        fma2(kvp[0][0], p0, w4); fma2(kvp[0][1], p0, w5);
        fma2(kvp[1][0], p1, w4); fma2(kvp[1][1], p1, w5);
        fma2(kvp[2][0], p2, w4); fma2(kvp[2][1], p2, w5);
    }

    // sim & attn
    const float* qsw = g_qsw + nd * 8;
    const float* qvw = g_qvw + nd * 12;
    float sim = 0.f;
    #pragma unroll
    for (int p = 0; p < 4; p++) {
        float2 k2 = up2(ksp[p]);
        sim = fmaf(qsw[2 * p], k2.x, sim);
        sim = fmaf(qsw[2 * p + 1], k2.y, sim);
    }
    #pragma unroll
    for (int p = 0; p < 2; p++)
        #pragma unroll
        for (int c = 0; c < 3; c++) {
            float2 k2 = up2(kvp[c][p]);
            sim = fmaf(qvw[(2 * p) * 3 + c], k2.x, sim);
            sim = fmaf(qvw[(2 * p + 1) * 3 + c], k2.y, sim);
        }
    float attn = expf(sim);
    g_attn[e] = attn;
    atomicAdd(&g_Z[nd], attn);
}

// =====================================================================
// Kernel 3 (V pass)
// smem: [0,6144)     VA: [i<16][t<16][24] = ss o0..15 | sv o0..7
//       [6144,9216)  VB: [i<8][t<16][24]  = vv o0..15 | vs o0..7
// =====================================================================
#define VSM_FLOATS 9216

__global__ void __launch_bounds__(EPB)
edge_v_kernel(const float* __restrict__ pos, const float* __restrict__ x,
              const float* __restrict__ Wv2,
              const int* __restrict__ esrc, const int* __restrict__ edst,
              float* __restrict__ out)
{
    extern __shared__ float smem[];
    float* sVA = smem;
    float* sVB = smem + 6144;
    const int tid = threadIdx.x;

    for (int idx = tid; idx < 6144; idx += EPB) {
        int i = idx / 384, r = idx - i * 384, t = r / 24, s = r - t * 24;
        int col = (s < 16) ? (i * 16 + s) : (384 + i * 8 + (s - 16));
        sVA[idx] = Wv2[t * 576 + col] * W2_SCALE;
    }
    for (int idx = tid; idx < 3072; idx += EPB) {
        int i = idx / 384, r = idx - i * 384, t = r / 24, s = r - t * 24;
        int col = (s < 16) ? (256 + i * 16 + s) : (512 + i * 8 + (s - 16));
        sVB[idx] = Wv2[t * 576 + col] * W2_SCALE;
    }
    __syncthreads();

    const ulonglong2* VA = (const ulonglong2*)sVA;   // [i*96 + t*6 + k]
    const ulonglong2* VB = (const ulonglong2*)sVB;

    const int e = blockIdx.x * EPB + tid;
    const int ns = esrc[e];
    const int nd = edst[e];

    float vx = pos[nd * 3 + 0] - pos[ns * 3 + 0];
    float vy = pos[nd * 3 + 1] - pos[ns * 3 + 1];
    float vz = pos[nd * 3 + 2] - pos[ns * 3 + 2];
    float d = sqrtf(vx * vx + vy * vy + vz * vz);
    if (d >= R_CUT) return;     // v == 0 exactly

    const float dsafe = fmaxf(d, 1e-6f);
    const float invd  = 1.0f / dsafe;
    const float vh0 = vx * invd, vh1 = vy * invd, vh2 = vz * invd;
    const float y10 = SQ3 * vh0, y11 = SQ3 * vh1, y12 = SQ3 * vh2;

    const float a_norm = g_attn[e] / g_Z[nd];

    u64t hv2[16];
    #pragma unroll
    for (int t = 0; t < 16; t++) hv2[t] = pkdup(__ldg(&g_hv[t * N_EDGES + e]));

    const float* xrow = x + ns * 40;
    u64t vsp[8];  u64t vvp[3][4];
    #pragma unroll
    for (int p = 0; p < 8; p++) vsp[p] = 0ull;
    #pragma unroll
    for (int c = 0; c < 3; c++)
        #pragma unroll
        for (int p = 0; p < 4; p++) vvp[c][p] = 0ull;

    // group A: i<16 (ss + sv), 12 independent chains
    #pragma unroll 1
    for (int i = 0; i < 16; i++) {
        float xi = __ldg(&xrow[i]);
        const ulonglong2* Wp = VA + i * 96;
        u64t w0=0,w1=0,w2=0,w3=0,w4=0,w5=0,w6=0,w7=0,w8=0,w9=0,w10=0,w11=0;
        #pragma unroll
        for (int t = 0; t < 16; t++) {
            const ulonglong2* q = Wp + t * 6;
            ulonglong2 q0 = q[0], q1 = q[1], q2 = q[2], q3 = q[3], q4 = q[4], q5 = q[5];
            u64t h = hv2[t];
            fma2(w0, h, q0.x); fma2(w1, h, q0.y);
            fma2(w2, h, q1.x); fma2(w3, h, q1.y);
            fma2(w4, h, q2.x); fma2(w5, h, q2.y);
            fma2(w6, h, q3.x); fma2(w7, h, q3.y);
            fma2(w8, h, q4.x); fma2(w9, h, q4.y);
            fma2(w10, h, q5.x); fma2(w11, h, q5.y);
        }
        u64t xi2 = pkdup(xi);
        fma2(vsp[0], xi2, w0); fma2(vsp[1], xi2, w1);
        fma2(vsp[2], xi2, w2); fma2(vsp[3], xi2, w3);
        fma2(vsp[4], xi2, w4); fma2(vsp[5], xi2, w5);
        fma2(vsp[6], xi2, w6); fma2(vsp[7], xi2, w7);
        u64t m0 = pkdup(xi * y10), m1 = pkdup(xi * y11), m2 = pkdup(xi * y12);
        fma2(vvp[0][0], m0, w8); fma2(vvp[0][1], m0, w9);
        fma2(vvp[0][2], m0, w10); fma2(vvp[0][3], m0, w11);
        fma2(vvp[1][0], m1, w8); fma2(vvp[1][1], m1, w9);
        fma2(vvp[1][2], m1, w10); fma2(vvp[1][3], m1, w11);
        fma2(vvp[2][0], m2, w8); fma2(vvp[2][1], m2, w9);
        fma2(vvp[2][2], m2, w10); fma2(vvp[2][3], m2, w11);
    }
    // group B: i<8 (vv + vs)
    #pragma unroll 1
    for (int i = 0; i < 8; i++) {
        float x0 = __ldg(&xrow[16 + i * 3 + 0]);
        float x1 = __ldg(&xrow[16 + i * 3 + 1]);
        float x2 = __ldg(&xrow[16 + i * 3 + 2]);
        float ui = x0 * vh0 + x1 * vh1 + x2 * vh2;
        const ulonglong2* Wp = VB + i * 96;
        u64t w0=0,w1=0,w2=0,w3=0,w4=0,w5=0,w6=0,w7=0,w8=0,w9=0,w10=0,w11=0;
        #pragma unroll
        for (int t = 0; t < 16; t++) {
            const ulonglong2* q = Wp + t * 6;
            ulonglong2 q0 = q[0], q1 = q[1], q2 = q[2], q3 = q[3], q4 = q[4], q5 = q[5];
            u64t h = hv2[t];
            fma2(w0, h, q0.x); fma2(w1, h, q0.y);
            fma2(w2, h, q1.x); fma2(w3, h, q1.y);
            fma2(w4, h, q2.x); fma2(w5, h, q2.y);
            fma2(w6, h, q3.x); fma2(w7, h, q3.y);
            fma2(w8, h, q4.x); fma2(w9, h, q4.y);
            fma2(w10, h, q5.x); fma2(w11, h, q5.y);
        }
        u64t u2 = pkdup(ui);
        fma2(vsp[0], u2, w0); fma2(vsp[1], u2, w1);
        fma2(vsp[2], u2, w2); fma2(vsp[3], u2, w3);
        fma2(vsp[4], u2, w4); fma2(vsp[5], u2, w5);
        fma2(vsp[6], u2, w6); fma2(vsp[7], u2, w7);
        u64t p0 = pkdup(x0), p1 = pkdup(x1), p2 = pkdup(x2);
        fma2(vvp[0][0], p0, w8); fma2(vvp[0][1], p0, w9);
        fma2(vvp[0][2], p0, w10); fma2(vvp[0][3], p0, w11);
        fma2(vvp[1][0], p1, w8); fma2(vvp[1][1], p1, w9);
        fma2(vvp[1][2], p1, w10); fma2(vvp[1][3], p1, w11);
        fma2(vvp[2][0], p2, w8); fma2(vvp[2][1], p2, w9);
        fma2(vvp[2][2], p2, w10); fma2(vvp[2][3], p2, w11);
    }

    // scatter a * v
    float* orow = out + nd * 40;
    #pragma unroll
    for (int p = 0; p < 8; p++) {
        float2 v2 = up2(vsp[p]);
        atomicAdd(&orow[2 * p],     a_norm * v2.x);
        atomicAdd(&orow[2 * p + 1], a_norm * v2.y);
    }
    #pragma unroll
    for (int p = 0; p < 4; p++)
        #pragma unroll
        for (int c = 0; c < 3; c++) {
            float2 v2 = up2(vvp[c][p]);
            atomicAdd(&orow[16 + (2 * p) * 3 + c],     a_norm * v2.x);
            atomicAdd(&orow[16 + (2 * p + 1) * 3 + c], a_norm * v2.y);
        }
}

// =====================================================================
extern "C" void kernel_launch(void* const* d_in, const int* in_sizes, int n_in,
                              void* d_out, int out_size)
{
    const float* pos   = (const float*)d_in[0];
    const float* x     = (const float*)d_in[1];
    const float* Wq_s  = (const float*)d_in[2];
    const float* Wq_v  = (const float*)d_in[3];
    const float* Wk1   = (const float*)d_in[4];
    const float* Wk2   = (const float*)d_in[5];
    const float* Wv1   = (const float*)d_in[6];
    const float* Wv2   = (const float*)d_in[7];
    const float* Ws_ss = (const float*)d_in[8];
    const float* Ws_vv = (const float*)d_in[9];
    const int*   esrc  = (const int*)d_in[10];
    const int*   edst  = (const int*)d_in[11];
    float* out = (float*)d_out;
    (void)in_sizes; (void)n_in; (void)out_size;

    const int ksm = KSM_FLOATS * (int)sizeof(float);   // 22528
    const int vsm = VSM_FLOATS * (int)sizeof(float);   // 36864
    cudaFuncSetAttribute(edge_k_kernel, cudaFuncAttributeMaxDynamicSharedMemorySize, ksm);
    cudaFuncSetAttribute(edge_v_kernel, cudaFuncAttributeMaxDynamicSharedMemorySize, vsm);

    void* zptr = nullptr;
    cudaGetSymbolAddress(&zptr, g_Z);
    cudaMemsetAsync(zptr, 0, N_NODES * sizeof(float), 0);
    cudaMemsetAsync(out, 0, N_NODES * 40 * sizeof(float), 0);

    node_prep_kernel<<<(N_NODES + 255) / 256, 256>>>(x, Wq_s, Wq_v, Ws_ss, Ws_vv);
    edge_k_kernel<<<N_EDGES / EPB, EPB, ksm>>>(pos, x, Wk1, Wk2, Wv1, esrc, edst);
    edge_v_kernel<<<N_EDGES / EPB, EPB, vsm>>>(pos, x, Wv2, esrc, edst, out);
}

// round 7
// speedup vs baseline: 1.1413x; 1.1413x over previous
#include <cuda_runtime.h>
#include <math.h>

#define N_NODES 16000
#define N_EDGES 256000
#define EPB 128

#define R_CUT 2.5f
#define SQ3   1.7320508075688772f
#define PI_F  3.14159265358979323846f

// ---- scratch (device globals; no allocations allowed) ----
__device__ float g_attn[N_EDGES];
__device__ float g_hv[16 * N_EDGES];      // V-net hidden, [t][e]
__device__ float g_Z[N_NODES];
__device__ float g_qsw[N_NODES * 8];
__device__ float g_qvw[N_NODES * 12];

// scales
#define INV_SQRT32 0.17677669529663687f
#define W2_SCALE   0.051031036307982884f  // (1/sqrt16)*(1/sqrt24)
#define INV_SQRT16 0.25f
#define INV_SQRT8  0.3535533905932738f
#define INV_FAN    0.11180339887498948f   // 1/sqrt(80)
#define RAD_COEF   5.059644256269407f     // sqrt(2/2.5)*sqrt(32)

// ---- packed fp32x2 helpers ----
typedef unsigned long long u64t;

__device__ __forceinline__ u64t pkdup(float a) {
    u64t r; asm("mov.b64 %0, {%1, %1};" : "=l"(r) : "f"(a)); return r;
}
__device__ __forceinline__ float2 up2(u64t v) {
    float2 r; asm("mov.b64 {%0, %1}, %2;" : "=f"(r.x), "=f"(r.y) : "l"(v)); return r;
}
__device__ __forceinline__ void fma2(u64t& d, u64t a, u64t b) {
    asm("fma.rn.f32x2 %0, %1, %2, %3;" : "=l"(d) : "l"(a), "l"(b), "l"(d));
}

__device__ __forceinline__ float silu_fast(float a) {
    return __fdividef(a, 1.f + __expf(-a));
}

// quad dot: one LDS.128 per t feeds two packed FMAs (cols 4Q..4Q+3)
__device__ __forceinline__ void dotq(const ulonglong2* __restrict__ cb,
                                     const u64t* __restrict__ h2,
                                     u64t& w0, u64t& w1) {
    w0 = 0ull; w1 = 0ull;
    #pragma unroll
    for (int t = 0; t < 16; t++) {
        ulonglong2 q = cb[t];
        fma2(w0, h2[t], q.x);
        fma2(w1, h2[t], q.y);
    }
}

// =====================================================================
// Kernel 1: per-node q (pre-contracted with Ws)
// =====================================================================
__global__ void node_prep_kernel(const float* __restrict__ x,
                                 const float* __restrict__ Wq_s,
                                 const float* __restrict__ Wq_v,
                                 const float* __restrict__ Ws_ss,
                                 const float* __restrict__ Ws_vv)
{
    int n = blockIdx.x * blockDim.x + threadIdx.x;
    if (n >= N_NODES) return;
    const float* xr = x + n * 40;

    float xs[16], xv[24];
    #pragma unroll
    for (int i = 0; i < 16; i++) xs[i] = xr[i];
    #pragma unroll
    for (int i = 0; i < 24; i++) xv[i] = xr[16 + i];

    float qs[8];
    #pragma unroll
    for (int o = 0; o < 8; o++) {
        float a = 0.f;
        #pragma unroll
        for (int i = 0; i < 16; i++) a = fmaf(xs[i], __ldg(&Wq_s[i * 8 + o]), a);
        qs[o] = a * INV_SQRT16;
    }
    float qv[12];
    #pragma unroll
    for (int o = 0; o < 4; o++)
        #pragma unroll
        for (int c = 0; c < 3; c++) {
            float a = 0.f;
            #pragma unroll
            for (int i = 0; i < 8; i++) a = fmaf(xv[i * 3 + c], __ldg(&Wq_v[i * 4 + o]), a);
            qv[o * 3 + c] = a * INV_SQRT8;
        }

    #pragma unroll
    for (int p = 0; p < 8; p++) {
        float a = 0.f;
        #pragma unroll
        for (int o = 0; o < 8; o++) a = fmaf(qs[o], __ldg(&Ws_ss[o * 8 + p]), a);
        g_qsw[n * 8 + p] = a * INV_FAN;
    }
    const float invfs = INV_FAN / SQ3;
    #pragma unroll
    for (int p = 0; p < 4; p++)
        #pragma unroll
        for (int c = 0; c < 3; c++) {
            float a = 0.f;
            #pragma unroll
            for (int o = 0; o < 4; o++) a = fmaf(qv[o * 3 + c], __ldg(&Ws_vv[o * 4 + p]), a);
            g_qvw[n * 12 + p * 3 + c] = a * invfs;
        }
}

// =====================================================================
// Kernel 2 (K pass): basis -> hk,hv; store hv; K tensor product -> attn, Z
// smem (floats): [0,512) Wk1 rows, [512,1024) Wv1 rows,
//                [1024,5632) Wk2 quads [Q][t] float4 (72 quads)
// =====================================================================
#define KSM_FLOATS 5632

__global__ void __launch_bounds__(EPB)
edge_k_kernel(const float* __restrict__ pos, const float* __restrict__ x,
              const float* __restrict__ Wk1, const float* __restrict__ Wk2,
              const float* __restrict__ Wv1,
              const int* __restrict__ esrc, const int* __restrict__ edst)
{
    extern __shared__ float smem[];
    float* sWk1f = smem;
    float* sWv1f = smem + 512;
    float* sWk2f = smem + 1024;
    const int tid = threadIdx.x;

    for (int idx = tid; idx < 512; idx += EPB) sWk1f[idx] = Wk1[idx] * INV_SQRT32;
    for (int idx = tid; idx < 512; idx += EPB) sWv1f[idx] = Wv1[idx] * INV_SQRT32;
    // quad layout: float idx -> Q=idx/64, t=(idx>>2)&15, c=idx&3, col=4Q+c
    for (int idx = tid; idx < 72 * 64; idx += EPB) {
        int Q = idx >> 6, t = (idx >> 2) & 15, c = idx & 3;
        sWk2f[idx] = Wk2[t * 288 + 4 * Q + c] * W2_SCALE;
    }
    __syncthreads();

    const ulonglong2* sWk1q = (const ulonglong2*)sWk1f;   // [n*4 + q]
    const ulonglong2* sWv1q = (const ulonglong2*)sWv1f;
    const ulonglong2* sWk2q = (const ulonglong2*)sWk2f;   // [Q*16 + t]

    const int e = blockIdx.x * EPB + tid;
    const int ns = esrc[e];
    const int nd = edst[e];

    float vx = pos[nd * 3 + 0] - pos[ns * 3 + 0];
    float vy = pos[nd * 3 + 1] - pos[ns * 3 + 1];
    float vz = pos[nd * 3 + 2] - pos[ns * 3 + 2];
    float d = sqrtf(vx * vx + vy * vy + vz * vz);

    if (d >= R_CUT) {           // rad==0 -> k=v=0 -> sim=0 -> attn=1
        g_attn[e] = 1.0f;
        atomicAdd(&g_Z[nd], 1.0f);
        return;
    }

    const float dsafe = fmaxf(d, 1e-6f);
    const float invd  = 1.0f / dsafe;
    const float vh0 = vx * invd, vh1 = vy * invd, vh2 = vz * invd;
    const float y10 = SQ3 * vh0, y11 = SQ3 * vh1, y12 = SQ3 * vh2;
    const float theta = (PI_F / R_CUT) * dsafe;
    const float coef  = RAD_COEF * invd;

    // ---- radial basis via Chebyshev recurrence; both hidden layers ----
    u64t akp[8], avp[8];
    #pragma unroll
    for (int t2 = 0; t2 < 8; t2++) { akp[t2] = 0ull; avp[t2] = 0ull; }
    float sth, cth;
    sincosf(theta, &sth, &cth);
    const float twoc = 2.0f * cth;
    float s_nm1 = 0.f, s_n = sth;
    #pragma unroll 1
    for (int n = 0; n < 32; n++) {
        float r = coef * s_n;
        u64t r2 = pkdup(r);
        const ulonglong2* wk = sWk1q + n * 4;
        const ulonglong2* wv = sWv1q + n * 4;
        #pragma unroll
        for (int q = 0; q < 4; q++) {
            ulonglong2 a = wk[q];
            fma2(akp[2 * q], r2, a.x);
            fma2(akp[2 * q + 1], r2, a.y);
            ulonglong2 b = wv[q];
            fma2(avp[2 * q], r2, b.x);
            fma2(avp[2 * q + 1], r2, b.y);
        }
        float s_nx = fmaf(twoc, s_n, -s_nm1);
        s_nm1 = s_n; s_n = s_nx;
    }
    // silu: hk kept packed; hv stored to global (frees regs)
    u64t hk2[16];
    #pragma unroll
    for (int t2 = 0; t2 < 8; t2++) {
        float2 a = up2(akp[t2]);
        hk2[2 * t2]     = pkdup(silu_fast(a.x));
        hk2[2 * t2 + 1] = pkdup(silu_fast(a.y));
        float2 b = up2(avp[t2]);
        g_hv[(2 * t2) * N_EDGES + e]     = silu_fast(b.x);
        g_hv[(2 * t2 + 1) * N_EDGES + e] = silu_fast(b.y);
    }

    // ---- source features in registers ----
    const float4* xr4 = (const float4*)(x + ns * 40);
    float xs[16];
    {
        float4 a = xr4[0], b = xr4[1], c = xr4[2], dd = xr4[3];
        xs[0]=a.x; xs[1]=a.y; xs[2]=a.z; xs[3]=a.w;
        xs[4]=b.x; xs[5]=b.y; xs[6]=b.z; xs[7]=b.w;
        xs[8]=c.x; xs[9]=c.y; xs[10]=c.z; xs[11]=c.w;
        xs[12]=dd.x; xs[13]=dd.y; xs[14]=dd.z; xs[15]=dd.w;
    }

    u64t ksp[4];  u64t kvp[3][2];
    #pragma unroll
    for (int p = 0; p < 4; p++) ksp[p] = 0ull;
    #pragma unroll
    for (int c = 0; c < 3; c++) { kvp[c][0] = 0ull; kvp[c][1] = 0ull; }

    // ss block: quads 2i, 2i+1 -> ksp[0..3]
    #pragma unroll
    for (int i = 0; i < 16; i++) {
        u64t xi2 = pkdup(xs[i]);
        u64t w0, w1;
        dotq(sWk2q + (2 * i) * 16, hk2, w0, w1);
        fma2(ksp[0], xi2, w0); fma2(ksp[1], xi2, w1);
        dotq(sWk2q + (2 * i + 1) * 16, hk2, w0, w1);
        fma2(ksp[2], xi2, w0); fma2(ksp[3], xi2, w1);
    }
    // sv block: quads 48+i: kv[o][c] += xs_i * w_o * y1c
    #pragma unroll
    for (int i = 0; i < 16; i++) {
        u64t xy0 = pkdup(xs[i] * y10), xy1 = pkdup(xs[i] * y11), xy2 = pkdup(xs[i] * y12);
        u64t w0, w1;
        dotq(sWk2q + (48 + i) * 16, hk2, w0, w1);
        fma2(kvp[0][0], xy0, w0); fma2(kvp[0][1], xy0, w1);
        fma2(kvp[1][0], xy1, w0); fma2(kvp[1][1], xy1, w1);
        fma2(kvp[2][0], xy2, w0); fma2(kvp[2][1], xy2, w1);
    }
    // vector features
    float xv[24];
    {
        float4 a = xr4[4], b = xr4[5], c = xr4[6], dd = xr4[7], ee = xr4[8], ff = xr4[9];
        xv[0]=a.x; xv[1]=a.y; xv[2]=a.z; xv[3]=a.w;
        xv[4]=b.x; xv[5]=b.y; xv[6]=b.z; xv[7]=b.w;
        xv[8]=c.x; xv[9]=c.y; xv[10]=c.z; xv[11]=c.w;
        xv[12]=dd.x; xv[13]=dd.y; xv[14]=dd.z; xv[15]=dd.w;
        xv[16]=ee.x; xv[17]=ee.y; xv[18]=ee.z; xv[19]=ee.w;
        xv[20]=ff.x; xv[21]=ff.y; xv[22]=ff.z; xv[23]=ff.w;
    }
    float uv[8];
    #pragma unroll
    for (int i = 0; i < 8; i++)
        uv[i] = xv[i*3+0]*vh0 + xv[i*3+1]*vh1 + xv[i*3+2]*vh2;

    // vv block: quads 32+2i, 33+2i (multiplier uv)
    #pragma unroll
    for (int i = 0; i < 8; i++) {
        u64t ui2 = pkdup(uv[i]);
        u64t w0, w1;
        dotq(sWk2q + (32 + 2 * i) * 16, hk2, w0, w1);
        fma2(ksp[0], ui2, w0); fma2(ksp[1], ui2, w1);
        dotq(sWk2q + (33 + 2 * i) * 16, hk2, w0, w1);
        fma2(ksp[2], ui2, w0); fma2(ksp[3], ui2, w1);
    }
    // vs block: quads 64+i: kv[o][c] += xv[i][c] * w_o
    #pragma unroll
    for (int i = 0; i < 8; i++) {
        u64t x02 = pkdup(xv[i*3+0]), x12 = pkdup(xv[i*3+1]), x22 = pkdup(xv[i*3+2]);
        u64t w0, w1;
        dotq(sWk2q + (64 + i) * 16, hk2, w0, w1);
        fma2(kvp[0][0], x02, w0); fma2(kvp[0][1], x02, w1);
        fma2(kvp[1][0], x12, w0); fma2(kvp[1][1], x12, w1);
        fma2(kvp[2][0], x22, w0); fma2(kvp[2][1], x22, w1);
    }

    // sim & attn
    const float* qsw = g_qsw + nd * 8;
    const float* qvw = g_qvw + nd * 12;
    float sim = 0.f;
    #pragma unroll
    for (int p = 0; p < 4; p++) {
        float2 k2 = up2(ksp[p]);
        sim = fmaf(qsw[2 * p], k2.x, sim);
        sim = fmaf(qsw[2 * p + 1], k2.y, sim);
    }
    #pragma unroll
    for (int p = 0; p < 2; p++)
        #pragma unroll
        for (int c = 0; c < 3; c++) {
            float2 k2 = up2(kvp[c][p]);
            sim = fmaf(qvw[(2 * p) * 3 + c], k2.x, sim);
            sim = fmaf(qvw[(2 * p + 1) * 3 + c], k2.y, sim);
        }
    float attn = __expf(sim);
    g_attn[e] = attn;
    atomicAdd(&g_Z[nd], attn);
}

// =====================================================================
// Kernel 3 (V pass): hv from scratch; V tensor product; scatter a*v
// smem: Wv2 quads [Q][t] float4, 144 quads -> 9216 floats
// =====================================================================
#define VSM_FLOATS 9216

__global__ void __launch_bounds__(EPB)
edge_v_kernel(const float* __restrict__ pos, const float* __restrict__ x,
              const float* __restrict__ Wv2,
              const int* __restrict__ esrc, const int* __restrict__ edst,
              float* __restrict__ out)
{
    extern __shared__ float smem[];
    float* sWv2f = smem;
    const int tid = threadIdx.x;

    for (int idx = tid; idx < 144 * 64; idx += EPB) {
        int Q = idx >> 6, t = (idx >> 2) & 15, c = idx & 3;
        sWv2f[idx] = Wv2[t * 576 + 4 * Q + c] * W2_SCALE;
    }
    __syncthreads();
    const ulonglong2* sWv2q = (const ulonglong2*)sWv2f;

    const int e = blockIdx.x * EPB + tid;
    const int ns = esrc[e];
    const int nd = edst[e];

    float vx = pos[nd * 3 + 0] - pos[ns * 3 + 0];
    float vy = pos[nd * 3 + 1] - pos[ns * 3 + 1];
    float vz = pos[nd * 3 + 2] - pos[ns * 3 + 2];
    float d = sqrtf(vx * vx + vy * vy + vz * vz);
    if (d >= R_CUT) return;     // v == 0 exactly

    const float dsafe = fmaxf(d, 1e-6f);
    const float invd  = 1.0f / dsafe;
    const float vh0 = vx * invd, vh1 = vy * invd, vh2 = vz * invd;
    const float y10 = SQ3 * vh0, y11 = SQ3 * vh1, y12 = SQ3 * vh2;

    const float a_norm = g_attn[e] / g_Z[nd];

    // hidden (precomputed by K pass)
    u64t hv2[16];
    #pragma unroll
    for (int t = 0; t < 16; t++) hv2[t] = pkdup(__ldg(&g_hv[t * N_EDGES + e]));

    const float4* xr4 = (const float4*)(x + ns * 40);
    float xs[16];
    {
        float4 a = xr4[0], b = xr4[1], c = xr4[2], dd = xr4[3];
        xs[0]=a.x; xs[1]=a.y; xs[2]=a.z; xs[3]=a.w;
        xs[4]=b.x; xs[5]=b.y; xs[6]=b.z; xs[7]=b.w;
        xs[8]=c.x; xs[9]=c.y; xs[10]=c.z; xs[11]=c.w;
        xs[12]=dd.x; xs[13]=dd.y; xs[14]=dd.z; xs[15]=dd.w;
    }

    u64t vsp[8];  u64t vvp[3][4];
    #pragma unroll
    for (int p = 0; p < 8; p++) vsp[p] = 0ull;
    #pragma unroll
    for (int c = 0; c < 3; c++)
        #pragma unroll
        for (int p = 0; p < 4; p++) vvp[c][p] = 0ull;

    // ss: quads 4i..4i+3 -> vsp[0..7]
    #pragma unroll
    for (int i = 0; i < 16; i++) {
        u64t xi2 = pkdup(xs[i]);
        #pragma unroll
        for (int qq = 0; qq < 4; qq++) {
            u64t w0, w1;
            dotq(sWv2q + (4 * i + qq) * 16, hv2, w0, w1);
            fma2(vsp[2 * qq], xi2, w0); fma2(vsp[2 * qq + 1], xi2, w1);
        }
    }
    // sv: quads 96+2i, 97+2i: vv[o][c] += xs_i * w_o * y1c
    #pragma unroll
    for (int i = 0; i < 16; i++) {
        u64t xy0 = pkdup(xs[i] * y10), xy1 = pkdup(xs[i] * y11), xy2 = pkdup(xs[i] * y12);
        #pragma unroll
        for (int qq = 0; qq < 2; qq++) {
            u64t w0, w1;
            dotq(sWv2q + (96 + 2 * i + qq) * 16, hv2, w0, w1);
            fma2(vvp[0][2 * qq], xy0, w0); fma2(vvp[0][2 * qq + 1], xy0, w1);
            fma2(vvp[1][2 * qq], xy1, w0); fma2(vvp[1][2 * qq + 1], xy1, w1);
            fma2(vvp[2][2 * qq], xy2, w0); fma2(vvp[2][2 * qq + 1], xy2, w1);
        }
    }

    float xv[24];
    {
        float4 a = xr4[4], b = xr4[5], c = xr4[6], dd = xr4[7], ee = xr4[8], ff = xr4[9];
        xv[0]=a.x; xv[1]=a.y; xv[2]=a.z; xv[3]=a.w;
        xv[4]=b.x; xv[5]=b.y; xv[6]=b.z; xv[7]=b.w;
        xv[8]=c.x; xv[9]=c.y; xv[10]=c.z; xv[11]=c.w;
        xv[12]=dd.x; xv[13]=dd.y; xv[14]=dd.z; xv[15]=dd.w;
        xv[16]=ee.x; xv[17]=ee.y; xv[18]=ee.z; xv[19]=ee.w;
        xv[20]=ff.x; xv[21]=ff.y; xv[22]=ff.z; xv[23]=ff.w;
    }
    float uv[8];
    #pragma unroll
    for (int i = 0; i < 8; i++)
        uv[i] = xv[i*3+0]*vh0 + xv[i*3+1]*vh1 + xv[i*3+2]*vh2;

    // vv: quads 64+4i..+3 (multiplier uv)
    #pragma unroll
    for (int i = 0; i < 8; i++) {
        u64t ui2 = pkdup(uv[i]);
        #pragma unroll
        for (int qq = 0; qq < 4; qq++) {
            u64t w0, w1;
            dotq(sWv2q + (64 + 4 * i + qq) * 16, hv2, w0, w1);
            fma2(vsp[2 * qq], ui2, w0); fma2(vsp[2 * qq + 1], ui2, w1);
        }
    }
    // vs: quads 128+2i, 129+2i: vv[o][c] += xv[i][c] * w_o
    #pragma unroll
    for (int i = 0; i < 8; i++) {
        u64t x02 = pkdup(xv[i*3+0]), x12 = pkdup(xv[i*3+1]), x22 = pkdup(xv[i*3+2]);
        #pragma unroll
        for (int qq = 0; qq < 2; qq++) {
            u64t w0, w1;
            dotq(sWv2q + (128 + 2 * i + qq) * 16, hv2, w0, w1);
            fma2(vvp[0][2 * qq], x02, w0); fma2(vvp[0][2 * qq + 1], x02, w1);
            fma2(vvp[1][2 * qq], x12, w0); fma2(vvp[1][2 * qq + 1], x12, w1);
            fma2(vvp[2][2 * qq], x22, w0); fma2(vvp[2][2 * qq + 1], x22, w1);
        }
    }

    // scatter a * v
    float* orow = out + nd * 40;
    #pragma unroll
    for (int p = 0; p < 8; p++) {
        float2 v2 = up2(vsp[p]);
        atomicAdd(&orow[2 * p],     a_norm * v2.x);
        atomicAdd(&orow[2 * p + 1], a_norm * v2.y);
    }
    #pragma unroll
    for (int p = 0; p < 4; p++)
        #pragma unroll
        for (int c = 0; c < 3; c++) {
            float2 v2 = up2(vvp[c][p]);
            atomicAdd(&orow[16 + (2 * p) * 3 + c],     a_norm * v2.x);
            atomicAdd(&orow[16 + (2 * p + 1) * 3 + c], a_norm * v2.y);
        }
}

// =====================================================================
extern "C" void kernel_launch(void* const* d_in, const int* in_sizes, int n_in,
                              void* d_out, int out_size)
{
    const float* pos   = (const float*)d_in[0];
    const float* x     = (const float*)d_in[1];
    const float* Wq_s  = (const float*)d_in[2];
    const float* Wq_v  = (const float*)d_in[3];
    const float* Wk1   = (const float*)d_in[4];
    const float* Wk2   = (const float*)d_in[5];
    const float* Wv1   = (const float*)d_in[6];
    const float* Wv2   = (const float*)d_in[7];
    const float* Ws_ss = (const float*)d_in[8];
    const float* Ws_vv = (const float*)d_in[9];
    const int*   esrc  = (const int*)d_in[10];
    const int*   edst  = (const int*)d_in[11];
    float* out = (float*)d_out;
    (void)in_sizes; (void)n_in; (void)out_size;

    const int ksm = KSM_FLOATS * (int)sizeof(float);   // 22528
    const int vsm = VSM_FLOATS * (int)sizeof(float);   // 36864
    cudaFuncSetAttribute(edge_k_kernel, cudaFuncAttributeMaxDynamicSharedMemorySize, ksm);
    cudaFuncSetAttribute(edge_v_kernel, cudaFuncAttributeMaxDynamicSharedMemorySize, vsm);

    void* zptr = nullptr;
    cudaGetSymbolAddress(&zptr, g_Z);
    cudaMemsetAsync(zptr, 0, N_NODES * sizeof(float), 0);
    cudaMemsetAsync(out, 0, N_NODES * 40 * sizeof(float), 0);

    node_prep_kernel<<<(N_NODES + 255) / 256, 256>>>(x, Wq_s, Wq_v, Ws_ss, Ws_vv);
    edge_k_kernel<<<N_EDGES / EPB, EPB, ksm>>>(pos, x, Wk1, Wk2, Wv1, esrc, edst);
    edge_v_kernel<<<N_EDGES / EPB, EPB, vsm>>>(pos, x, Wv2, esrc, edst, out);
}